// round 12
// baseline (speedup 1.0000x reference)
#include <cuda_runtime.h>
#include <cuda_bf16.h>
#include <stdint.h>
#include <cstdint>
#include <math.h>

#define N_SAMPLES 32768
#define FEAT 768
#define CODES 64
#define PAGES 8192
#define OFF_LOSS 25165824        // 32768*768
#define OFF_IDX  25165825
#define MARGIN 0.02f

// argmin smem layout (bytes): 64-row blocks
#define SM_ZA   0u               // 64 x 72 bf16 = 9216
#define SM_CB   9216u            // 2 stages x 18432
#define SM_TM   46080u           // bf16 [64 rows][128 halves] = 16384
#define SM_RED  62464u           // 256 floats
#define SM_TOTAL 63488u

// ---------------- scratch (device globals; no allocation allowed) ----------
__device__ __align__(128) float g_cn[PAGES * CODES];          // normalized codebook fp32
__device__ float g_cn2[PAGES];
__device__ __align__(128) __nv_bfloat16 g_cnb[PAGES * CODES]; // bf16 coarse copy
__device__ __align__(128) float g_zq[N_SAMPLES * CODES];
__device__ float g_zq2[N_SAMPLES];
__device__ __align__(128) __nv_bfloat16 g_zqb[N_SAMPLES * CODES];
__device__ int   g_idx[N_SAMPLES];
__device__ float g_winT[FEAT * CODES];       // w_in transposed: [f][c]
__device__ float g_woutT[CODES * FEAT];      // w_out transposed: [c][f]
__device__ __align__(128) float g_U[PAGES * FEAT];   // cn @ w_out^T + b_out
__device__ float g_partial[512];

__device__ __forceinline__ float warp_sum(float v) {
    #pragma unroll
    for (int o = 16; o; o >>= 1) v += __shfl_down_sync(0xffffffffu, v, o);
    return v;
}

// ---------------- PTX helpers ----------------------------------------------
__device__ __forceinline__ void ldm4(unsigned addr, unsigned& r0, unsigned& r1,
                                     unsigned& r2, unsigned& r3) {
    asm volatile("ldmatrix.sync.aligned.m8n8.x4.shared.b16 {%0,%1,%2,%3}, [%4];"
                 : "=r"(r0), "=r"(r1), "=r"(r2), "=r"(r3) : "r"(addr));
}
__device__ __forceinline__ void mma_bf16(float* c, const unsigned* a,
                                         unsigned b0, unsigned b1) {
    asm volatile(
        "mma.sync.aligned.m16n8k16.row.col.f32.bf16.bf16.f32 "
        "{%0,%1,%2,%3},{%4,%5,%6,%7},{%8,%9},{%0,%1,%2,%3};"
        : "+f"(c[0]), "+f"(c[1]), "+f"(c[2]), "+f"(c[3])
        : "r"(a[0]), "r"(a[1]), "r"(a[2]), "r"(a[3]), "r"(b0), "r"(b1));
}
__device__ __forceinline__ void cpa16(unsigned d, const void* s) {
    asm volatile("cp.async.cg.shared.global [%0], [%1], 16;" :: "r"(d), "l"(s) : "memory");
}
__device__ __forceinline__ void cpa_commit() {
    asm volatile("cp.async.commit_group;" ::: "memory");
}
__device__ __forceinline__ void cpa_wait0() {
    asm volatile("cp.async.wait_group 0;" ::: "memory");
}
__device__ __forceinline__ void cpa_wait1() {
    asm volatile("cp.async.wait_group 1;" ::: "memory");
}

// ---------------- normalize codebook: 4 pages per block -------------------
__global__ void cb_norm_kernel(const float* __restrict__ cb) {
    __shared__ float red[4][2];
    int tid = threadIdx.x;
    int g = tid >> 6;
    int c = tid & 63;
    int p = blockIdx.x * 4 + g;
    float v = cb[p * 64 + c];
    float s = warp_sum(v * v);
    if ((tid & 31) == 0) red[g][(tid >> 5) & 1] = s;
    __syncthreads();
    float norm = sqrtf(red[g][0] + red[g][1]);
    float nv = v / norm;
    g_cn[p * 64 + c] = nv;
    g_cnb[p * 64 + c] = __float2bfloat16(nv);
    __syncthreads();
    float s2 = warp_sum(nv * nv);
    if ((tid & 31) == 0) red[g][(tid >> 5) & 1] = s2;
    __syncthreads();
    if (c == 0) g_cn2[p] = red[g][0] + red[g][1];
}

// ---------------- transpose the two weight matrices ------------------------
__global__ void prep_w_kernel(const float* __restrict__ w_in,
                              const float* __restrict__ w_out) {
    int i = blockIdx.x * 256 + threadIdx.x;
    int f = i / 64, c = i & 63;
    g_winT[f * 64 + c]  = w_in[c * 768 + f];
    g_woutT[c * 768 + f] = w_out[f * 64 + c];
}

// ---------------- zq: cp.async double-buffered fp32 GEMM + normalize -------
__global__ __launch_bounds__(256, 2) void zq_kernel(const float* __restrict__ z,
                                                    const float* __restrict__ b_in) {
    extern __shared__ float sm[];
    float* zS = sm;                 // 2 * 8704 floats
    float* wS = sm + 17408;         // 2 * 4352 floats
    float* proj = sm;               // [128][65], reuses zS after GEMM
    unsigned baseS = (unsigned)__cvta_generic_to_shared(sm);
    unsigned zSB = baseS;
    unsigned wSB = baseS + 17408u * 4u;

    int tid = threadIdx.x;
    int tx = tid & 15, ty = tid >> 4;
    long row0 = (long)blockIdx.x * 128;

    float acc[8][4];
    #pragma unroll
    for (int i = 0; i < 8; i++)
        #pragma unroll
        for (int j = 0; j < 4; j++) acc[i][j] = 0.f;
    float bb[4];
    #pragma unroll
    for (int j = 0; j < 4; j++) bb[j] = b_in[tx * 4 + j];

    {
        #pragma unroll
        for (int k2 = 0; k2 < 8; k2++) {
            int i = tid + k2 * 256; int r = i >> 4, ch = i & 15;
            cpa16(zSB + (unsigned)(r * 68 + ch * 4) * 4u,
                  z + (row0 + r) * 768 + ch * 4);
        }
        #pragma unroll
        for (int k2 = 0; k2 < 4; k2++) {
            int i = tid + k2 * 256; int f = i >> 4, ch = i & 15;
            cpa16(wSB + (unsigned)(f * 68 + ch * 4) * 4u,
                  g_winT + f * 64 + ch * 4);
        }
        cpa_commit();
    }

    for (int kt = 0; kt < 12; kt++) {
        if (kt < 11) {
            int nb = (kt + 1) & 1;
            int f0n = (kt + 1) * 64;
            #pragma unroll
            for (int k2 = 0; k2 < 8; k2++) {
                int i = tid + k2 * 256; int r = i >> 4, ch = i & 15;
                cpa16(zSB + (unsigned)(nb * 8704 + r * 68 + ch * 4) * 4u,
                      z + (row0 + r) * 768 + f0n + ch * 4);
            }
            #pragma unroll
            for (int k2 = 0; k2 < 4; k2++) {
                int i = tid + k2 * 256; int f = i >> 4, ch = i & 15;
                cpa16(wSB + (unsigned)(nb * 4352 + f * 68 + ch * 4) * 4u,
                      g_winT + (f0n + f) * 64 + ch * 4);
            }
            cpa_commit();
            cpa_wait1();
        } else {
            cpa_wait0();
        }
        __syncthreads();
        const float* zb = zS + (kt & 1) * 8704;
        const float* wb = wS + (kt & 1) * 4352;
        #pragma unroll 4
        for (int f = 0; f < 64; f++) {
            float4 b4 = *(const float4*)&wb[f * 68 + tx * 4];
            float a[8];
            #pragma unroll
            for (int i = 0; i < 8; i++) a[i] = zb[(ty + 16 * i) * 68 + f];
            #pragma unroll
            for (int i = 0; i < 8; i++) {
                acc[i][0] = fmaf(a[i], b4.x, acc[i][0]);
                acc[i][1] = fmaf(a[i], b4.y, acc[i][1]);
                acc[i][2] = fmaf(a[i], b4.z, acc[i][2]);
                acc[i][3] = fmaf(a[i], b4.w, acc[i][3]);
            }
        }
        __syncthreads();
    }
    #pragma unroll
    for (int i = 0; i < 8; i++)
        #pragma unroll
        for (int j = 0; j < 4; j++)
            proj[(ty + 16 * i) * 65 + tx * 4 + j] = acc[i][j] + bb[j];
    __syncthreads();
    if (tid < 128) {
        int r = tid;
        float s = 0.f;
        #pragma unroll 8
        for (int c = 0; c < 64; c++) { float v = proj[r * 65 + c]; s = fmaf(v, v, s); }
        float nrm = sqrtf(s);
        float s2 = 0.f;
        for (int c = 0; c < 64; c++) {
            float v = proj[r * 65 + c] / nrm;
            g_zq[(row0 + r) * 64 + c] = v;
            g_zqb[(row0 + r) * 64 + c] = __float2bfloat16(v);
            s2 = fmaf(v, v, s2);
        }
        g_zq2[row0 + r] = s2;
    }
}

// ---------------- exact fp32 rescore (round-1 arithmetic order) ------------
__device__ __forceinline__ float exact_d(int n, int p) {
    const float4* zr = (const float4*)(g_zq + n * 64);
    const float4* cr = (const float4*)(g_cn + p * 64);
    float dot = 0.f;
    #pragma unroll
    for (int c = 0; c < 16; c++) {
        float4 a = zr[c], b = cr[c];
        dot = fmaf(a.x, b.x, dot);
        dot = fmaf(a.y, b.y, dot);
        dot = fmaf(a.z, b.z, dot);
        dot = fmaf(a.w, b.w, dot);
    }
    return fmaf(-2.f, dot, g_zq2[n] + g_cn2[p]);
}

// ---------------- single-pass coarse GEMM + tile-max + exact argmin + loss -
// 64 rows/CTA, 512 blocks, 3 CTAs/SM. Warp = 16 rows x 64 pages (rg=warp>>1,
// pg=warp&1). 2-stage cp.async pipeline, double-barrier; epilogue overlaps
// next tile's loads. tm = per-(row, 64-page half) coarse max (bf16 round-up).
__global__ __launch_bounds__(256, 3) void argmin_kernel() {
    extern __shared__ char smc[];
    __nv_bfloat16* za = (__nv_bfloat16*)smc;
    __nv_bfloat16* tm = (__nv_bfloat16*)(smc + SM_TM);
    float* red = (float*)(smc + SM_RED);
    unsigned zaS = (unsigned)__cvta_generic_to_shared(smc);
    unsigned cbS = zaS + SM_CB;

    int tid = threadIdx.x, lane = tid & 31, warp = tid >> 5;
    int rg = warp >> 1, pg = warp & 1;
    int g = lane >> 2, tg = lane & 3;
    int row0 = blockIdx.x * 64;

    for (int i = tid; i < 64 * 64; i += 256) {
        int r = i >> 6, c = i & 63;
        za[r * 72 + c] = g_zqb[(row0 + r) * 64 + c];
    }

    int a_row = rg * 16 + (lane & 7) + ((lane >> 3) & 1) * 8;
    unsigned aoff = (unsigned)(a_row * 72 + (lane >> 4) * 8) * 2u;
    int b_page = pg * 64 + (lane & 7) + (lane >> 4) * 8;
    unsigned bk = (unsigned)(((lane >> 3) & 1) * 8);
    unsigned boff[4];
    #pragma unroll
    for (int q = 0; q < 4; q++) boff[q] = (unsigned)((b_page + q * 16) * 72 + bk) * 2u;

    float rmax[2];
    rmax[0] = rmax[1] = -1e30f;

    // prologue: tiles 0,1 into stages 0,1
    #pragma unroll
    for (int s = 0; s < 2; s++) {
        const __nv_bfloat16* src = g_cnb + s * 8192;
        #pragma unroll
        for (int k2 = 0; k2 < 4; k2++) {
            int i = tid + k2 * 256; int r = i >> 3, ch = i & 7;
            cpa16(cbS + (unsigned)s * 18432u + (unsigned)(r * 72 + ch * 8) * 2u,
                  src + r * 64 + ch * 8);
        }
        cpa_commit();
    }

    for (int t = 0; t < 64; t++) {
        if (t < 63) cpa_wait1(); else cpa_wait0();
        __syncthreads();                       // tile t visible; za visible (t==0)
        unsigned curS = cbS + (unsigned)(t & 1) * 18432u;

        float acc[8][4];
        #pragma unroll
        for (int j = 0; j < 8; j++)
            #pragma unroll
            for (int k = 0; k < 4; k++) acc[j][k] = 0.f;

        #pragma unroll
        for (int ks = 0; ks < 4; ks++) {
            unsigned a[4], bq[4][4];
            ldm4(zaS + aoff + ks * 32, a[0], a[1], a[2], a[3]);
            #pragma unroll
            for (int q = 0; q < 4; q++)
                ldm4(curS + boff[q] + ks * 32, bq[q][0], bq[q][1], bq[q][2], bq[q][3]);
            #pragma unroll
            for (int q = 0; q < 4; q++) {
                mma_bf16(acc[2 * q],     a, bq[q][0], bq[q][1]);
                mma_bf16(acc[2 * q + 1], a, bq[q][2], bq[q][3]);
            }
        }
        __syncthreads();                       // all warps done reading buf t&1
        if (t + 2 < 64) {                      // refill freed buffer
            const __nv_bfloat16* src = g_cnb + (t + 2) * 8192;
            unsigned dstS = cbS + (unsigned)(t & 1) * 18432u;
            #pragma unroll
            for (int k2 = 0; k2 < 4; k2++) {
                int i = tid + k2 * 256; int r = i >> 3, ch = i & 7;
                cpa16(dstS + (unsigned)(r * 72 + ch * 8) * 2u, src + r * 64 + ch * 8);
            }
            cpa_commit();
        }
        // epilogue overlaps the cp.async above (tm/regs only, no cb access)
        float lm[2];
        lm[0] = lm[1] = -1e30f;
        #pragma unroll
        for (int j = 0; j < 8; j++) {
            lm[0] = fmaxf(lm[0], fmaxf(acc[j][0], acc[j][1]));
            lm[1] = fmaxf(lm[1], fmaxf(acc[j][2], acc[j][3]));
        }
        #pragma unroll
        for (int e = 0; e < 2; e++) {
            rmax[e] = fmaxf(rmax[e], lm[e]);
            lm[e] = fmaxf(lm[e], __shfl_xor_sync(0xffffffffu, lm[e], 1));
            lm[e] = fmaxf(lm[e], __shfl_xor_sync(0xffffffffu, lm[e], 2));
        }
        if (tg == 0) {
            int h = t * 2 + pg;
            #pragma unroll
            for (int e = 0; e < 2; e++) {
                int r = rg * 16 + g + e * 8;
                tm[r * 128 + h] = __float2bfloat16_ru(lm[e]);
            }
        }
    }

    // per-row threshold = exact rowmax - MARGIN
    #pragma unroll
    for (int e = 0; e < 2; e++) {
        rmax[e] = fmaxf(rmax[e], __shfl_xor_sync(0xffffffffu, rmax[e], 1));
        rmax[e] = fmaxf(rmax[e], __shfl_xor_sync(0xffffffffu, rmax[e], 2));
    }
    __syncthreads();                           // also makes last tm writes visible
    if (tg == 0) {
        #pragma unroll
        for (int e = 0; e < 2; e++) {
            int r = rg * 16 + g + e * 8;
            red[r * 2 + pg] = rmax[e];
        }
    }
    __syncthreads();
    if (tid < 64) red[128 + tid] = fmaxf(red[tid * 2], red[tid * 2 + 1]) - MARGIN;
    __syncthreads();

    // candidate scan: each warp owns 8 rows
    for (int rr = 0; rr < 8; rr++) {
        int r = warp * 8 + rr;
        float thr = red[128 + r];
        float bdd = 1e30f;
        int bii = PAGES;
        #pragma unroll
        for (int hb = 0; hb < 128; hb += 32) {
            float m = __bfloat162float(tm[r * 128 + hb + lane]);
            unsigned mask = __ballot_sync(0xffffffffu, m >= thr);
            while (mask) {
                int h = hb + (__ffs(mask) - 1);
                mask &= mask - 1;
                int pb = h * 64;
                #pragma unroll
                for (int q = 0; q < 2; q++) {
                    int p = pb + lane + q * 32;
                    float d = exact_d(row0 + r, p);
                    if (d < bdd || (d == bdd && p < bii)) { bdd = d; bii = p; }
                }
            }
        }
        #pragma unroll
        for (int s = 16; s; s >>= 1) {
            float od = __shfl_xor_sync(0xffffffffu, bdd, s);
            int   oi = __shfl_xor_sync(0xffffffffu, bii, s);
            if (od < bdd || (od == bdd && oi < bii)) { bdd = od; bii = oi; }
        }
        if (lane == 0) {
            g_idx[row0 + r] = bii;
            red[192 + r] = bdd;               // winner's exact squared distance
        }
    }

    // deterministic per-block loss partial
    __syncthreads();
    for (int o = 32; o; o >>= 1) {
        if (tid < o) red[192 + tid] += red[192 + tid + o];
        __syncthreads();
    }
    if (tid == 0) g_partial[blockIdx.x] = red[192];
}

// ---------------- U = cn @ w_out^T + b_out (per page, once) ----------------
__global__ __launch_bounds__(256, 2) void u_kernel(const float* __restrict__ b_out) {
    extern __shared__ float sm[];
    float* codeS = sm;          // 8192 floats: [128 pages][64]
    float* wS = sm + 8192;      // 8192 floats: [64][128]
    int tid = threadIdx.x, tx = tid & 15, ty = tid >> 4;
    int f0 = blockIdx.x * 128;
    int p0 = blockIdx.y * 128;
    for (int i = tid; i < 8192; i += 256) {
        int r = i >> 6, c = i & 63;
        codeS[r * 64 + c] = g_cn[(p0 + r) * 64 + c];
    }
    for (int i = tid; i < 8192; i += 256) {
        int c = i >> 7, f = i & 127;
        wS[c * 128 + f] = g_woutT[c * 768 + f0 + f];
    }
    __syncthreads();
    float acc[8][8];
    #pragma unroll
    for (int i = 0; i < 8; i++)
        #pragma unroll
        for (int j = 0; j < 8; j++) acc[i][j] = 0.f;
    #pragma unroll 4
    for (int c = 0; c < 64; c++) {
        float a[8], b[8];
        #pragma unroll
        for (int i = 0; i < 8; i++) a[i] = codeS[(ty + 16 * i) * 64 + c];
        #pragma unroll
        for (int j = 0; j < 8; j++) b[j] = wS[c * 128 + tx + 16 * j];
        #pragma unroll
        for (int i = 0; i < 8; i++)
            #pragma unroll
            for (int j = 0; j < 8; j++)
                acc[i][j] = fmaf(a[i], b[j], acc[i][j]);
    }
    float bo[8];
    #pragma unroll
    for (int j = 0; j < 8; j++) bo[j] = b_out[f0 + tx + 16 * j];
    #pragma unroll
    for (int i = 0; i < 8; i++)
        #pragma unroll
        for (int j = 0; j < 8; j++)
            g_U[(p0 + ty + 16 * i) * 768 + f0 + tx + 16 * j] = acc[i][j] + bo[j];
}

// ---------------- out[n] = U[idx[n]] (pure gather, float4) -----------------
__global__ void gather_kernel(float* __restrict__ out) {
    int n = blockIdx.x;
    int t = threadIdx.x;          // 192 threads, 192 float4 = 768 floats
    const float4* src = (const float4*)(g_U + g_idx[n] * 768);
    float4* dst = (float4*)(out + (long)n * 768);
    dst[t] = src[t];
}

__global__ void finalize_kernel(float* __restrict__ outbuf) {
    if (threadIdx.x == 0) {
        float s = 0.f;
        for (int k = 0; k < 512; k++) s += g_partial[k];
        outbuf[OFF_LOSS] = 1.25f * (s / 2097152.0f);
    }
}

__global__ void idx_kernel(float* __restrict__ outbuf) {
    int i = blockIdx.x * 256 + threadIdx.x;
    outbuf[OFF_IDX + i] = (float)g_idx[i];
}

// ---------------- launch ----------------------------------------------------
extern "C" void kernel_launch(void* const* d_in, const int* in_sizes, int n_in,
                              void* d_out, int out_size) {
    const float* z     = (const float*)d_in[0];
    const float* w_in  = (const float*)d_in[1];
    const float* b_in  = (const float*)d_in[2];
    const float* w_out = (const float*)d_in[3];
    const float* b_out = (const float*)d_in[4];
    const float* cb    = (const float*)d_in[5];
    float* out = (float*)d_out;

    cudaFuncSetAttribute(zq_kernel, cudaFuncAttributeMaxDynamicSharedMemorySize, 104448);
    cudaFuncSetAttribute(argmin_kernel, cudaFuncAttributeMaxDynamicSharedMemorySize, SM_TOTAL);
    cudaFuncSetAttribute(u_kernel, cudaFuncAttributeMaxDynamicSharedMemorySize, 65536);

    cb_norm_kernel<<<PAGES / 4, 256>>>(cb);
    prep_w_kernel<<<FEAT * CODES / 256, 256>>>(w_in, w_out);
    u_kernel<<<dim3(6, PAGES / 128), 256, 65536>>>(b_out);
    zq_kernel<<<N_SAMPLES / 128, 256, 104448>>>(z, b_in);
    argmin_kernel<<<N_SAMPLES / 64, 256, SM_TOTAL>>>();
    gather_kernel<<<N_SAMPLES, 192>>>(out);
    finalize_kernel<<<1, 1>>>(out);
    idx_kernel<<<N_SAMPLES / 256, 256>>>(out);
}

// round 13
// speedup vs baseline: 1.2374x; 1.2374x over previous
#include <cuda_runtime.h>
#include <cuda_bf16.h>
#include <stdint.h>
#include <cstdint>
#include <math.h>

#define N_SAMPLES 32768
#define FEAT 768
#define CODES 64
#define PAGES 8192
#define OFF_LOSS 25165824        // 32768*768
#define OFF_IDX  25165825
#define MARGIN 0.02f

// argmin smem layout (bytes): 128-row blocks, 2-stage cb pipeline
#define SM_ZA   0u               // 128 x 72 bf16 = 18432
#define SM_CB   18432u           // 2 stages x 18432
#define SM_TM   55296u           // bf16 [128 rows][128 halves] = 32768
#define SM_RED  88064u           // 512 floats
#define SM_TOTAL 90112u

// ---------------- scratch (device globals; no allocation allowed) ----------
__device__ __align__(128) float g_cn[PAGES * CODES];          // normalized codebook fp32
__device__ float g_cn2[PAGES];
__device__ __align__(128) __nv_bfloat16 g_cnb[PAGES * CODES]; // bf16 coarse copy
__device__ __align__(128) float g_zq[N_SAMPLES * CODES];
__device__ float g_zq2[N_SAMPLES];
__device__ __align__(128) __nv_bfloat16 g_zqb[N_SAMPLES * CODES];
__device__ int   g_idx[N_SAMPLES];
__device__ float g_winT[FEAT * CODES];       // w_in transposed: [f][c]
__device__ float g_woutT[CODES * FEAT];      // w_out transposed: [c][f]
__device__ __align__(128) float g_U[PAGES * FEAT];   // cn @ w_out^T + b_out
__device__ float g_partial[256];

__device__ __forceinline__ float warp_sum(float v) {
    #pragma unroll
    for (int o = 16; o; o >>= 1) v += __shfl_down_sync(0xffffffffu, v, o);
    return v;
}

// ---------------- PTX helpers ----------------------------------------------
__device__ __forceinline__ void ldm4(unsigned addr, unsigned& r0, unsigned& r1,
                                     unsigned& r2, unsigned& r3) {
    asm volatile("ldmatrix.sync.aligned.m8n8.x4.shared.b16 {%0,%1,%2,%3}, [%4];"
                 : "=r"(r0), "=r"(r1), "=r"(r2), "=r"(r3) : "r"(addr));
}
__device__ __forceinline__ void mma_bf16(float* c, const unsigned* a,
                                         unsigned b0, unsigned b1) {
    asm volatile(
        "mma.sync.aligned.m16n8k16.row.col.f32.bf16.bf16.f32 "
        "{%0,%1,%2,%3},{%4,%5,%6,%7},{%8,%9},{%0,%1,%2,%3};"
        : "+f"(c[0]), "+f"(c[1]), "+f"(c[2]), "+f"(c[3])
        : "r"(a[0]), "r"(a[1]), "r"(a[2]), "r"(a[3]), "r"(b0), "r"(b1));
}
__device__ __forceinline__ void cpa16(unsigned d, const void* s) {
    asm volatile("cp.async.cg.shared.global [%0], [%1], 16;" :: "r"(d), "l"(s) : "memory");
}
__device__ __forceinline__ void cpa_commit() {
    asm volatile("cp.async.commit_group;" ::: "memory");
}
__device__ __forceinline__ void cpa_wait0() {
    asm volatile("cp.async.wait_group 0;" ::: "memory");
}
__device__ __forceinline__ void cpa_wait1() {
    asm volatile("cp.async.wait_group 1;" ::: "memory");
}

// ---------------- normalize codebook: 4 pages per block -------------------
__global__ void cb_norm_kernel(const float* __restrict__ cb) {
    __shared__ float red[4][2];
    int tid = threadIdx.x;
    int g = tid >> 6;
    int c = tid & 63;
    int p = blockIdx.x * 4 + g;
    float v = cb[p * 64 + c];
    float s = warp_sum(v * v);
    if ((tid & 31) == 0) red[g][(tid >> 5) & 1] = s;
    __syncthreads();
    float norm = sqrtf(red[g][0] + red[g][1]);
    float nv = v / norm;
    g_cn[p * 64 + c] = nv;
    g_cnb[p * 64 + c] = __float2bfloat16(nv);
    __syncthreads();
    float s2 = warp_sum(nv * nv);
    if ((tid & 31) == 0) red[g][(tid >> 5) & 1] = s2;
    __syncthreads();
    if (c == 0) g_cn2[p] = red[g][0] + red[g][1];
}

// ---------------- transpose the two weight matrices ------------------------
__global__ void prep_w_kernel(const float* __restrict__ w_in,
                              const float* __restrict__ w_out) {
    int i = blockIdx.x * 256 + threadIdx.x;
    int f = i / 64, c = i & 63;
    g_winT[f * 64 + c]  = w_in[c * 768 + f];
    g_woutT[c * 768 + f] = w_out[f * 64 + c];
}

// ---------------- zq: cp.async double-buffered fp32 GEMM + normalize -------
__global__ __launch_bounds__(256, 2) void zq_kernel(const float* __restrict__ z,
                                                    const float* __restrict__ b_in) {
    extern __shared__ float sm[];
    float* zS = sm;                 // 2 * 8704 floats
    float* wS = sm + 17408;         // 2 * 4352 floats
    float* proj = sm;               // [128][65], reuses zS after GEMM
    unsigned baseS = (unsigned)__cvta_generic_to_shared(sm);
    unsigned zSB = baseS;
    unsigned wSB = baseS + 17408u * 4u;

    int tid = threadIdx.x;
    int tx = tid & 15, ty = tid >> 4;
    long row0 = (long)blockIdx.x * 128;

    float acc[8][4];
    #pragma unroll
    for (int i = 0; i < 8; i++)
        #pragma unroll
        for (int j = 0; j < 4; j++) acc[i][j] = 0.f;
    float bb[4];
    #pragma unroll
    for (int j = 0; j < 4; j++) bb[j] = b_in[tx * 4 + j];

    {
        #pragma unroll
        for (int k2 = 0; k2 < 8; k2++) {
            int i = tid + k2 * 256; int r = i >> 4, ch = i & 15;
            cpa16(zSB + (unsigned)(r * 68 + ch * 4) * 4u,
                  z + (row0 + r) * 768 + ch * 4);
        }
        #pragma unroll
        for (int k2 = 0; k2 < 4; k2++) {
            int i = tid + k2 * 256; int f = i >> 4, ch = i & 15;
            cpa16(wSB + (unsigned)(f * 68 + ch * 4) * 4u,
                  g_winT + f * 64 + ch * 4);
        }
        cpa_commit();
    }

    for (int kt = 0; kt < 12; kt++) {
        if (kt < 11) {
            int nb = (kt + 1) & 1;
            int f0n = (kt + 1) * 64;
            #pragma unroll
            for (int k2 = 0; k2 < 8; k2++) {
                int i = tid + k2 * 256; int r = i >> 4, ch = i & 15;
                cpa16(zSB + (unsigned)(nb * 8704 + r * 68 + ch * 4) * 4u,
                      z + (row0 + r) * 768 + f0n + ch * 4);
            }
            #pragma unroll
            for (int k2 = 0; k2 < 4; k2++) {
                int i = tid + k2 * 256; int f = i >> 4, ch = i & 15;
                cpa16(wSB + (unsigned)(nb * 4352 + f * 68 + ch * 4) * 4u,
                      g_winT + (f0n + f) * 64 + ch * 4);
            }
            cpa_commit();
            cpa_wait1();
        } else {
            cpa_wait0();
        }
        __syncthreads();
        const float* zb = zS + (kt & 1) * 8704;
        const float* wb = wS + (kt & 1) * 4352;
        #pragma unroll 4
        for (int f = 0; f < 64; f++) {
            float4 b4 = *(const float4*)&wb[f * 68 + tx * 4];
            float a[8];
            #pragma unroll
            for (int i = 0; i < 8; i++) a[i] = zb[(ty + 16 * i) * 68 + f];
            #pragma unroll
            for (int i = 0; i < 8; i++) {
                acc[i][0] = fmaf(a[i], b4.x, acc[i][0]);
                acc[i][1] = fmaf(a[i], b4.y, acc[i][1]);
                acc[i][2] = fmaf(a[i], b4.z, acc[i][2]);
                acc[i][3] = fmaf(a[i], b4.w, acc[i][3]);
            }
        }
        __syncthreads();
    }
    #pragma unroll
    for (int i = 0; i < 8; i++)
        #pragma unroll
        for (int j = 0; j < 4; j++)
            proj[(ty + 16 * i) * 65 + tx * 4 + j] = acc[i][j] + bb[j];
    __syncthreads();
    if (tid < 128) {
        int r = tid;
        float s = 0.f;
        #pragma unroll 8
        for (int c = 0; c < 64; c++) { float v = proj[r * 65 + c]; s = fmaf(v, v, s); }
        float nrm = sqrtf(s);
        float s2 = 0.f;
        for (int c = 0; c < 64; c++) {
            float v = proj[r * 65 + c] / nrm;
            g_zq[(row0 + r) * 64 + c] = v;
            g_zqb[(row0 + r) * 64 + c] = __float2bfloat16(v);
            s2 = fmaf(v, v, s2);
        }
        g_zq2[row0 + r] = s2;
    }
}

// ---------------- exact fp32 rescore (round-1 arithmetic order) ------------
__device__ __forceinline__ float exact_d(int n, int p) {
    const float4* zr = (const float4*)(g_zq + n * 64);
    const float4* cr = (const float4*)(g_cn + p * 64);
    float dot = 0.f;
    #pragma unroll
    for (int c = 0; c < 16; c++) {
        float4 a = zr[c], b = cr[c];
        dot = fmaf(a.x, b.x, dot);
        dot = fmaf(a.y, b.y, dot);
        dot = fmaf(a.z, b.z, dot);
        dot = fmaf(a.w, b.w, dot);
    }
    return fmaf(-2.f, dot, g_zq2[n] + g_cn2[p]);
}

// ---------------- single-pass coarse GEMM + tile-max + exact argmin + loss -
// R8 structure: 128 rows/CTA, 8 warps (warp = 32 rows x 64 pages), 2-stage
// cp.async double buffer with the NEXT tile issued BEFORE computing the
// current one (full load/compute overlap). tm = per-(row, 64-page half)
// coarse max (bf16 round-up); threshold filter; exact fp32 rescore; winner
// distance doubles as the loss contribution.
__global__ __launch_bounds__(256, 2) void argmin_kernel() {
    extern __shared__ char smc[];
    __nv_bfloat16* za = (__nv_bfloat16*)smc;
    __nv_bfloat16* tm = (__nv_bfloat16*)(smc + SM_TM);
    float* red = (float*)(smc + SM_RED);
    unsigned zaS = (unsigned)__cvta_generic_to_shared(smc);
    unsigned cbS0 = zaS + SM_CB;
    unsigned cbS1 = cbS0 + 18432u;

    int tid = threadIdx.x, lane = tid & 31, warp = tid >> 5;
    int rg = warp >> 1, pg = warp & 1;
    int g = lane >> 2, tg = lane & 3;
    int row0 = blockIdx.x * 128;

    for (int i = tid; i < 128 * 64; i += 256) {
        int r = i >> 6, c = i & 63;
        za[r * 72 + c] = g_zqb[(row0 + r) * 64 + c];
    }

    int a_row = rg * 32 + (lane & 7) + ((lane >> 3) & 1) * 8;
    unsigned aoff0 = (unsigned)(a_row * 72 + (lane >> 4) * 8) * 2u;
    unsigned aoff1 = aoff0 + 16u * 72u * 2u;
    int b_page = pg * 64 + (lane & 7) + (lane >> 4) * 8;
    unsigned bk = (unsigned)(((lane >> 3) & 1) * 8);
    unsigned boff[4];
    #pragma unroll
    for (int q = 0; q < 4; q++) boff[q] = (unsigned)((b_page + q * 16) * 72 + bk) * 2u;

    float rmax[4];
    #pragma unroll
    for (int e = 0; e < 4; e++) rmax[e] = -1e30f;

    __syncthreads();
    {   // prologue: tile 0 -> buffer 0
        const __nv_bfloat16* src = g_cnb;
        #pragma unroll
        for (int k2 = 0; k2 < 4; k2++) {
            int i = tid + k2 * 256; int r = i >> 3, ch = i & 7;
            cpa16(cbS0 + (unsigned)(r * 72 + ch * 8) * 2u, src + r * 64 + ch * 8);
        }
        cpa_commit();
    }
    for (int t = 0; t < 64; t++) {
        int cur = t & 1;
        unsigned curS = cur ? cbS1 : cbS0;
        cpa_wait0();
        __syncthreads();
        if (t < 63) {   // issue NEXT tile before compute -> full overlap
            const __nv_bfloat16* src = g_cnb + (t + 1) * 8192;
            unsigned dstS = cur ? cbS0 : cbS1;
            #pragma unroll
            for (int k2 = 0; k2 < 4; k2++) {
                int i = tid + k2 * 256; int r = i >> 3, ch = i & 7;
                cpa16(dstS + (unsigned)(r * 72 + ch * 8) * 2u, src + r * 64 + ch * 8);
            }
            cpa_commit();
        }
        float acc[2][8][4];
        #pragma unroll
        for (int mt = 0; mt < 2; mt++)
            #pragma unroll
            for (int j = 0; j < 8; j++)
                #pragma unroll
                for (int k = 0; k < 4; k++) acc[mt][j][k] = 0.f;

        #pragma unroll
        for (int ks = 0; ks < 4; ks++) {
            unsigned a0[4], a1[4], bq[4][4];
            ldm4(zaS + aoff0 + ks * 32, a0[0], a0[1], a0[2], a0[3]);
            ldm4(zaS + aoff1 + ks * 32, a1[0], a1[1], a1[2], a1[3]);
            #pragma unroll
            for (int q = 0; q < 4; q++)
                ldm4(curS + boff[q] + ks * 32, bq[q][0], bq[q][1], bq[q][2], bq[q][3]);
            #pragma unroll
            for (int q = 0; q < 4; q++) {
                mma_bf16(acc[0][2 * q],     a0, bq[q][0], bq[q][1]);
                mma_bf16(acc[0][2 * q + 1], a0, bq[q][2], bq[q][3]);
                mma_bf16(acc[1][2 * q],     a1, bq[q][0], bq[q][1]);
                mma_bf16(acc[1][2 * q + 1], a1, bq[q][2], bq[q][3]);
            }
        }
        // per-(row-elem, this 64-page half) local max
        float lm[4];
        #pragma unroll
        for (int e = 0; e < 4; e++) lm[e] = -1e30f;
        #pragma unroll
        for (int mt = 0; mt < 2; mt++)
            #pragma unroll
            for (int j = 0; j < 8; j++) {
                lm[mt * 2]     = fmaxf(lm[mt * 2],     fmaxf(acc[mt][j][0], acc[mt][j][1]));
                lm[mt * 2 + 1] = fmaxf(lm[mt * 2 + 1], fmaxf(acc[mt][j][2], acc[mt][j][3]));
            }
        #pragma unroll
        for (int e = 0; e < 4; e++) {
            rmax[e] = fmaxf(rmax[e], lm[e]);
            lm[e] = fmaxf(lm[e], __shfl_xor_sync(0xffffffffu, lm[e], 1));
            lm[e] = fmaxf(lm[e], __shfl_xor_sync(0xffffffffu, lm[e], 2));
        }
        if (tg == 0) {
            int h = t * 2 + pg;
            #pragma unroll
            for (int e = 0; e < 4; e++) {
                int r = rg * 32 + (e >> 1) * 16 + g + (e & 1) * 8;
                tm[r * 128 + h] = __float2bfloat16_ru(lm[e]);
            }
        }
    }

    // per-row threshold = exact rowmax - MARGIN
    #pragma unroll
    for (int e = 0; e < 4; e++) {
        rmax[e] = fmaxf(rmax[e], __shfl_xor_sync(0xffffffffu, rmax[e], 1));
        rmax[e] = fmaxf(rmax[e], __shfl_xor_sync(0xffffffffu, rmax[e], 2));
    }
    __syncthreads();
    if (tg == 0) {
        #pragma unroll
        for (int e = 0; e < 4; e++) {
            int r = rg * 32 + (e >> 1) * 16 + g + (e & 1) * 8;
            red[r * 2 + pg] = rmax[e];
        }
    }
    __syncthreads();
    if (tid < 128) red[256 + tid] = fmaxf(red[tid * 2], red[tid * 2 + 1]) - MARGIN;
    __syncthreads();

    // candidate scan: each warp owns 16 rows
    for (int rr = 0; rr < 16; rr++) {
        int r = warp * 16 + rr;
        float thr = red[256 + r];
        float bdd = 1e30f;
        int bii = PAGES;
        #pragma unroll
        for (int hb = 0; hb < 128; hb += 32) {
            float m = __bfloat162float(tm[r * 128 + hb + lane]);
            unsigned mask = __ballot_sync(0xffffffffu, m >= thr);
            while (mask) {
                int h = hb + (__ffs(mask) - 1);
                mask &= mask - 1;
                int pb = h * 64;
                #pragma unroll
                for (int q = 0; q < 2; q++) {
                    int p = pb + lane + q * 32;
                    float d = exact_d(row0 + r, p);
                    if (d < bdd || (d == bdd && p < bii)) { bdd = d; bii = p; }
                }
            }
        }
        #pragma unroll
        for (int s = 16; s; s >>= 1) {
            float od = __shfl_xor_sync(0xffffffffu, bdd, s);
            int   oi = __shfl_xor_sync(0xffffffffu, bii, s);
            if (od < bdd || (od == bdd && oi < bii)) { bdd = od; bii = oi; }
        }
        if (lane == 0) {
            g_idx[row0 + r] = bii;
            red[384 + r] = bdd;               // winner's exact squared distance
        }
    }

    // deterministic per-block loss partial
    __syncthreads();
    for (int o = 64; o; o >>= 1) {
        if (tid < o) red[384 + tid] += red[384 + tid + o];
        __syncthreads();
    }
    if (tid == 0) g_partial[blockIdx.x] = red[384];
}

// ---------------- U = cn @ w_out^T + b_out (per page, once) ----------------
__global__ __launch_bounds__(256, 2) void u_kernel(const float* __restrict__ b_out) {
    extern __shared__ float sm[];
    float* codeS = sm;          // 8192 floats: [128 pages][64]
    float* wS = sm + 8192;      // 8192 floats: [64][128]
    int tid = threadIdx.x, tx = tid & 15, ty = tid >> 4;
    int f0 = blockIdx.x * 128;
    int p0 = blockIdx.y * 128;
    for (int i = tid; i < 8192; i += 256) {
        int r = i >> 6, c = i & 63;
        codeS[r * 64 + c] = g_cn[(p0 + r) * 64 + c];
    }
    for (int i = tid; i < 8192; i += 256) {
        int c = i >> 7, f = i & 127;
        wS[c * 128 + f] = g_woutT[c * 768 + f0 + f];
    }
    __syncthreads();
    float acc[8][8];
    #pragma unroll
    for (int i = 0; i < 8; i++)
        #pragma unroll
        for (int j = 0; j < 8; j++) acc[i][j] = 0.f;
    #pragma unroll 4
    for (int c = 0; c < 64; c++) {
        float a[8], b[8];
        #pragma unroll
        for (int i = 0; i < 8; i++) a[i] = codeS[(ty + 16 * i) * 64 + c];
        #pragma unroll
        for (int j = 0; j < 8; j++) b[j] = wS[c * 128 + tx + 16 * j];
        #pragma unroll
        for (int i = 0; i < 8; i++)
            #pragma unroll
            for (int j = 0; j < 8; j++)
                acc[i][j] = fmaf(a[i], b[j], acc[i][j]);
    }
    float bo[8];
    #pragma unroll
    for (int j = 0; j < 8; j++) bo[j] = b_out[f0 + tx + 16 * j];
    #pragma unroll
    for (int i = 0; i < 8; i++)
        #pragma unroll
        for (int j = 0; j < 8; j++)
            g_U[(p0 + ty + 16 * i) * 768 + f0 + tx + 16 * j] = acc[i][j] + bo[j];
}

// ---------------- out[n] = U[idx[n]] (pure gather, float4) -----------------
__global__ void gather_kernel(float* __restrict__ out) {
    int n = blockIdx.x;
    int t = threadIdx.x;          // 192 threads, 192 float4 = 768 floats
    const float4* src = (const float4*)(g_U + g_idx[n] * 768);
    float4* dst = (float4*)(out + (long)n * 768);
    dst[t] = src[t];
}

__global__ void finalize_kernel(float* __restrict__ outbuf) {
    if (threadIdx.x == 0) {
        float s = 0.f;
        for (int k = 0; k < 256; k++) s += g_partial[k];
        outbuf[OFF_LOSS] = 1.25f * (s / 2097152.0f);
    }
}

__global__ void idx_kernel(float* __restrict__ outbuf) {
    int i = blockIdx.x * 256 + threadIdx.x;
    outbuf[OFF_IDX + i] = (float)g_idx[i];
}

// ---------------- launch ----------------------------------------------------
extern "C" void kernel_launch(void* const* d_in, const int* in_sizes, int n_in,
                              void* d_out, int out_size) {
    const float* z     = (const float*)d_in[0];
    const float* w_in  = (const float*)d_in[1];
    const float* b_in  = (const float*)d_in[2];
    const float* w_out = (const float*)d_in[3];
    const float* b_out = (const float*)d_in[4];
    const float* cb    = (const float*)d_in[5];
    float* out = (float*)d_out;

    cudaFuncSetAttribute(zq_kernel, cudaFuncAttributeMaxDynamicSharedMemorySize, 104448);
    cudaFuncSetAttribute(argmin_kernel, cudaFuncAttributeMaxDynamicSharedMemorySize, SM_TOTAL);
    cudaFuncSetAttribute(u_kernel, cudaFuncAttributeMaxDynamicSharedMemorySize, 65536);

    cb_norm_kernel<<<PAGES / 4, 256>>>(cb);
    prep_w_kernel<<<FEAT * CODES / 256, 256>>>(w_in, w_out);
    u_kernel<<<dim3(6, PAGES / 128), 256, 65536>>>(b_out);
    zq_kernel<<<N_SAMPLES / 128, 256, 104448>>>(z, b_in);
    argmin_kernel<<<N_SAMPLES / 128, 256, SM_TOTAL>>>();
    gather_kernel<<<N_SAMPLES, 192>>>(out);
    finalize_kernel<<<1, 1>>>(out);
    idx_kernel<<<N_SAMPLES / 256, 256>>>(out);
}

// round 14
// speedup vs baseline: 1.2808x; 1.0350x over previous
#include <cuda_runtime.h>
#include <cuda_bf16.h>
#include <stdint.h>
#include <cstdint>
#include <math.h>

#define N_SAMPLES 32768
#define FEAT 768
#define CODES 64
#define PAGES 8192
#define OFF_LOSS 25165824        // 32768*768
#define OFF_IDX  25165825
#define MARGIN 0.02f

// argmin smem layout (bytes): 128-row blocks, 2-stage cb pipeline
#define SM_ZA   0u               // 128 x 72 bf16 = 18432
#define SM_CB   18432u           // 2 stages x 18432
#define SM_TM   55296u           // bf16 [128 rows][128 halves] = 32768
#define SM_RED  88064u           // 512 floats
#define SM_TOTAL 90112u

// ---------------- scratch (device globals; no allocation allowed) ----------
__device__ __align__(128) float g_cn[PAGES * CODES];          // normalized codebook fp32
__device__ float g_cn2[PAGES];
__device__ __align__(128) __nv_bfloat16 g_cnb[PAGES * CODES]; // bf16 coarse copy
__device__ __align__(128) float g_zq[N_SAMPLES * CODES];
__device__ float g_zq2[N_SAMPLES];
__device__ __align__(128) __nv_bfloat16 g_zqb[N_SAMPLES * CODES];
__device__ int   g_idx[N_SAMPLES];
__device__ float g_winT[FEAT * CODES];       // w_in transposed: [f][c]
__device__ float g_woutT[CODES * FEAT];      // w_out transposed: [c][f]
__device__ __align__(128) float g_U[PAGES * FEAT];   // cn @ w_out^T + b_out
__device__ float g_partial[256];

__device__ __forceinline__ float warp_sum(float v) {
    #pragma unroll
    for (int o = 16; o; o >>= 1) v += __shfl_down_sync(0xffffffffu, v, o);
    return v;
}

// ---------------- PTX helpers ----------------------------------------------
__device__ __forceinline__ void ldm4(unsigned addr, unsigned& r0, unsigned& r1,
                                     unsigned& r2, unsigned& r3) {
    asm volatile("ldmatrix.sync.aligned.m8n8.x4.shared.b16 {%0,%1,%2,%3}, [%4];"
                 : "=r"(r0), "=r"(r1), "=r"(r2), "=r"(r3) : "r"(addr));
}
__device__ __forceinline__ void mma_bf16(float* c, const unsigned* a,
                                         unsigned b0, unsigned b1) {
    asm volatile(
        "mma.sync.aligned.m16n8k16.row.col.f32.bf16.bf16.f32 "
        "{%0,%1,%2,%3},{%4,%5,%6,%7},{%8,%9},{%0,%1,%2,%3};"
        : "+f"(c[0]), "+f"(c[1]), "+f"(c[2]), "+f"(c[3])
        : "r"(a[0]), "r"(a[1]), "r"(a[2]), "r"(a[3]), "r"(b0), "r"(b1));
}
__device__ __forceinline__ void cpa16(unsigned d, const void* s) {
    asm volatile("cp.async.cg.shared.global [%0], [%1], 16;" :: "r"(d), "l"(s) : "memory");
}
__device__ __forceinline__ void cpa_commit() {
    asm volatile("cp.async.commit_group;" ::: "memory");
}
__device__ __forceinline__ void cpa_wait0() {
    asm volatile("cp.async.wait_group 0;" ::: "memory");
}
__device__ __forceinline__ void cpa_wait1() {
    asm volatile("cp.async.wait_group 1;" ::: "memory");
}

// ---------------- normalize codebook: 4 pages per block -------------------
__global__ void cb_norm_kernel(const float* __restrict__ cb) {
    __shared__ float red[4][2];
    int tid = threadIdx.x;
    int g = tid >> 6;
    int c = tid & 63;
    int p = blockIdx.x * 4 + g;
    float v = cb[p * 64 + c];
    float s = warp_sum(v * v);
    if ((tid & 31) == 0) red[g][(tid >> 5) & 1] = s;
    __syncthreads();
    float norm = sqrtf(red[g][0] + red[g][1]);
    float nv = v / norm;
    g_cn[p * 64 + c] = nv;
    g_cnb[p * 64 + c] = __float2bfloat16(nv);
    __syncthreads();
    float s2 = warp_sum(nv * nv);
    if ((tid & 31) == 0) red[g][(tid >> 5) & 1] = s2;
    __syncthreads();
    if (c == 0) g_cn2[p] = red[g][0] + red[g][1];
}

// ---------------- transpose the two weight matrices ------------------------
__global__ void prep_w_kernel(const float* __restrict__ w_in,
                              const float* __restrict__ w_out) {
    int i = blockIdx.x * 256 + threadIdx.x;
    int f = i / 64, c = i & 63;
    g_winT[f * 64 + c]  = w_in[c * 768 + f];
    g_woutT[c * 768 + f] = w_out[f * 64 + c];
}

// ---------------- zq: cp.async double-buffered fp32 GEMM + normalize -------
__global__ __launch_bounds__(256, 2) void zq_kernel(const float* __restrict__ z,
                                                    const float* __restrict__ b_in) {
    extern __shared__ float sm[];
    float* zS = sm;                 // 2 * 8704 floats
    float* wS = sm + 17408;         // 2 * 4352 floats
    float* proj = sm;               // [128][65], reuses zS after GEMM
    unsigned baseS = (unsigned)__cvta_generic_to_shared(sm);
    unsigned zSB = baseS;
    unsigned wSB = baseS + 17408u * 4u;

    int tid = threadIdx.x;
    int tx = tid & 15, ty = tid >> 4;
    long row0 = (long)blockIdx.x * 128;

    float acc[8][4];
    #pragma unroll
    for (int i = 0; i < 8; i++)
        #pragma unroll
        for (int j = 0; j < 4; j++) acc[i][j] = 0.f;
    float bb[4];
    #pragma unroll
    for (int j = 0; j < 4; j++) bb[j] = b_in[tx * 4 + j];

    {
        #pragma unroll
        for (int k2 = 0; k2 < 8; k2++) {
            int i = tid + k2 * 256; int r = i >> 4, ch = i & 15;
            cpa16(zSB + (unsigned)(r * 68 + ch * 4) * 4u,
                  z + (row0 + r) * 768 + ch * 4);
        }
        #pragma unroll
        for (int k2 = 0; k2 < 4; k2++) {
            int i = tid + k2 * 256; int f = i >> 4, ch = i & 15;
            cpa16(wSB + (unsigned)(f * 68 + ch * 4) * 4u,
                  g_winT + f * 64 + ch * 4);
        }
        cpa_commit();
    }

    for (int kt = 0; kt < 12; kt++) {
        if (kt < 11) {
            int nb = (kt + 1) & 1;
            int f0n = (kt + 1) * 64;
            #pragma unroll
            for (int k2 = 0; k2 < 8; k2++) {
                int i = tid + k2 * 256; int r = i >> 4, ch = i & 15;
                cpa16(zSB + (unsigned)(nb * 8704 + r * 68 + ch * 4) * 4u,
                      z + (row0 + r) * 768 + f0n + ch * 4);
            }
            #pragma unroll
            for (int k2 = 0; k2 < 4; k2++) {
                int i = tid + k2 * 256; int f = i >> 4, ch = i & 15;
                cpa16(wSB + (unsigned)(nb * 4352 + f * 68 + ch * 4) * 4u,
                      g_winT + (f0n + f) * 64 + ch * 4);
            }
            cpa_commit();
            cpa_wait1();
        } else {
            cpa_wait0();
        }
        __syncthreads();
        const float* zb = zS + (kt & 1) * 8704;
        const float* wb = wS + (kt & 1) * 4352;
        #pragma unroll 4
        for (int f = 0; f < 64; f++) {
            float4 b4 = *(const float4*)&wb[f * 68 + tx * 4];
            float a[8];
            #pragma unroll
            for (int i = 0; i < 8; i++) a[i] = zb[(ty + 16 * i) * 68 + f];
            #pragma unroll
            for (int i = 0; i < 8; i++) {
                acc[i][0] = fmaf(a[i], b4.x, acc[i][0]);
                acc[i][1] = fmaf(a[i], b4.y, acc[i][1]);
                acc[i][2] = fmaf(a[i], b4.z, acc[i][2]);
                acc[i][3] = fmaf(a[i], b4.w, acc[i][3]);
            }
        }
        __syncthreads();
    }
    #pragma unroll
    for (int i = 0; i < 8; i++)
        #pragma unroll
        for (int j = 0; j < 4; j++)
            proj[(ty + 16 * i) * 65 + tx * 4 + j] = acc[i][j] + bb[j];
    __syncthreads();
    if (tid < 128) {
        int r = tid;
        float s = 0.f;
        #pragma unroll 8
        for (int c = 0; c < 64; c++) { float v = proj[r * 65 + c]; s = fmaf(v, v, s); }
        float nrm = sqrtf(s);
        float s2 = 0.f;
        for (int c = 0; c < 64; c++) {
            float v = proj[r * 65 + c] / nrm;
            g_zq[(row0 + r) * 64 + c] = v;
            g_zqb[(row0 + r) * 64 + c] = __float2bfloat16(v);
            s2 = fmaf(v, v, s2);
        }
        g_zq2[row0 + r] = s2;
    }
}

// ---------------- exact fp32 rescore (round-1 arithmetic order) ------------
__device__ __forceinline__ float exact_d(int n, int p) {
    const float4* zr = (const float4*)(g_zq + n * 64);
    const float4* cr = (const float4*)(g_cn + p * 64);
    float dot = 0.f;
    #pragma unroll
    for (int c = 0; c < 16; c++) {
        float4 a = zr[c], b = cr[c];
        dot = fmaf(a.x, b.x, dot);
        dot = fmaf(a.y, b.y, dot);
        dot = fmaf(a.z, b.z, dot);
        dot = fmaf(a.w, b.w, dot);
    }
    return fmaf(-2.f, dot, g_zq2[n] + g_cn2[p]);
}

// ---------------- single-pass coarse GEMM + tile-max + exact argmin + loss -
// 128 rows/CTA, 8 warps (warp = 32 rows x 64 pages). A fragments hoisted to
// registers (tile-invariant); per-tile max folded per 16-page group so only
// 16 transient accumulators live. 2-stage cp.async double buffer, next tile
// issued before compute. tm = per-(row, 64-page half) coarse max (round-up).
__global__ __launch_bounds__(256, 2) void argmin_kernel() {
    extern __shared__ char smc[];
    __nv_bfloat16* za = (__nv_bfloat16*)smc;
    __nv_bfloat16* tm = (__nv_bfloat16*)(smc + SM_TM);
    float* red = (float*)(smc + SM_RED);
    unsigned zaS = (unsigned)__cvta_generic_to_shared(smc);
    unsigned cbS0 = zaS + SM_CB;
    unsigned cbS1 = cbS0 + 18432u;

    int tid = threadIdx.x, lane = tid & 31, warp = tid >> 5;
    int rg = warp >> 1, pg = warp & 1;
    int g = lane >> 2, tg = lane & 3;
    int row0 = blockIdx.x * 128;

    for (int i = tid; i < 128 * 64; i += 256) {
        int r = i >> 6, c = i & 63;
        za[r * 72 + c] = g_zqb[(row0 + r) * 64 + c];
    }

    int a_row = rg * 32 + (lane & 7) + ((lane >> 3) & 1) * 8;
    unsigned aoff0 = (unsigned)(a_row * 72 + (lane >> 4) * 8) * 2u;
    unsigned aoff1 = aoff0 + 16u * 72u * 2u;
    int b_page = pg * 64 + (lane & 7) + (lane >> 4) * 8;
    unsigned bk = (unsigned)(((lane >> 3) & 1) * 8);
    unsigned boff[4];
    #pragma unroll
    for (int q = 0; q < 4; q++) boff[q] = (unsigned)((b_page + q * 16) * 72 + bk) * 2u;

    float rmax[4];
    #pragma unroll
    for (int e = 0; e < 4; e++) rmax[e] = -1e30f;

    __syncthreads();                       // za complete

    // hoist A fragments (tile-invariant) into registers: 32 regs
    unsigned A0[4][4], A1[4][4];
    #pragma unroll
    for (int ks = 0; ks < 4; ks++) {
        ldm4(zaS + aoff0 + ks * 32, A0[ks][0], A0[ks][1], A0[ks][2], A0[ks][3]);
        ldm4(zaS + aoff1 + ks * 32, A1[ks][0], A1[ks][1], A1[ks][2], A1[ks][3]);
    }

    {   // prologue: tile 0 -> buffer 0
        const __nv_bfloat16* src = g_cnb;
        #pragma unroll
        for (int k2 = 0; k2 < 4; k2++) {
            int i = tid + k2 * 256; int r = i >> 3, ch = i & 7;
            cpa16(cbS0 + (unsigned)(r * 72 + ch * 8) * 2u, src + r * 64 + ch * 8);
        }
        cpa_commit();
    }
    for (int t = 0; t < 64; t++) {
        int cur = t & 1;
        unsigned curS = cur ? cbS1 : cbS0;
        cpa_wait0();
        __syncthreads();
        if (t < 63) {   // issue NEXT tile before compute -> full overlap
            const __nv_bfloat16* src = g_cnb + (t + 1) * 8192;
            unsigned dstS = cur ? cbS0 : cbS1;
            #pragma unroll
            for (int k2 = 0; k2 < 4; k2++) {
                int i = tid + k2 * 256; int r = i >> 3, ch = i & 7;
                cpa16(dstS + (unsigned)(r * 72 + ch * 8) * 2u, src + r * 64 + ch * 8);
            }
            cpa_commit();
        }

        float lm[4];
        #pragma unroll
        for (int e = 0; e < 4; e++) lm[e] = -1e30f;

        #pragma unroll
        for (int q = 0; q < 4; q++) {       // 16 pages per group
            float acc[2][2][4];
            #pragma unroll
            for (int mt = 0; mt < 2; mt++)
                #pragma unroll
                for (int jn = 0; jn < 2; jn++)
                    #pragma unroll
                    for (int k = 0; k < 4; k++) acc[mt][jn][k] = 0.f;
            #pragma unroll
            for (int ks = 0; ks < 4; ks++) {
                unsigned bq0, bq1, bq2, bq3;
                ldm4(curS + boff[q] + ks * 32, bq0, bq1, bq2, bq3);
                mma_bf16(acc[0][0], A0[ks], bq0, bq1);
                mma_bf16(acc[0][1], A0[ks], bq2, bq3);
                mma_bf16(acc[1][0], A1[ks], bq0, bq1);
                mma_bf16(acc[1][1], A1[ks], bq2, bq3);
            }
            #pragma unroll
            for (int mt = 0; mt < 2; mt++)
                #pragma unroll
                for (int jn = 0; jn < 2; jn++) {
                    lm[mt * 2]     = fmaxf(lm[mt * 2],     fmaxf(acc[mt][jn][0], acc[mt][jn][1]));
                    lm[mt * 2 + 1] = fmaxf(lm[mt * 2 + 1], fmaxf(acc[mt][jn][2], acc[mt][jn][3]));
                }
        }

        #pragma unroll
        for (int e = 0; e < 4; e++) {
            rmax[e] = fmaxf(rmax[e], lm[e]);
            lm[e] = fmaxf(lm[e], __shfl_xor_sync(0xffffffffu, lm[e], 1));
            lm[e] = fmaxf(lm[e], __shfl_xor_sync(0xffffffffu, lm[e], 2));
        }
        if (tg == 0) {
            int h = t * 2 + pg;
            #pragma unroll
            for (int e = 0; e < 4; e++) {
                int r = rg * 32 + (e >> 1) * 16 + g + (e & 1) * 8;
                tm[r * 128 + h] = __float2bfloat16_ru(lm[e]);
            }
        }
    }

    // per-row threshold = exact rowmax - MARGIN
    #pragma unroll
    for (int e = 0; e < 4; e++) {
        rmax[e] = fmaxf(rmax[e], __shfl_xor_sync(0xffffffffu, rmax[e], 1));
        rmax[e] = fmaxf(rmax[e], __shfl_xor_sync(0xffffffffu, rmax[e], 2));
    }
    __syncthreads();
    if (tg == 0) {
        #pragma unroll
        for (int e = 0; e < 4; e++) {
            int r = rg * 32 + (e >> 1) * 16 + g + (e & 1) * 8;
            red[r * 2 + pg] = rmax[e];
        }
    }
    __syncthreads();
    if (tid < 128) red[256 + tid] = fmaxf(red[tid * 2], red[tid * 2 + 1]) - MARGIN;
    __syncthreads();

    // candidate scan: each warp owns 16 rows
    for (int rr = 0; rr < 16; rr++) {
        int r = warp * 16 + rr;
        float thr = red[256 + r];
        float bdd = 1e30f;
        int bii = PAGES;
        #pragma unroll
        for (int hb = 0; hb < 128; hb += 32) {
            float m = __bfloat162float(tm[r * 128 + hb + lane]);
            unsigned mask = __ballot_sync(0xffffffffu, m >= thr);
            while (mask) {
                int h = hb + (__ffs(mask) - 1);
                mask &= mask - 1;
                int pb = h * 64;
                #pragma unroll
                for (int q = 0; q < 2; q++) {
                    int p = pb + lane + q * 32;
                    float d = exact_d(row0 + r, p);
                    if (d < bdd || (d == bdd && p < bii)) { bdd = d; bii = p; }
                }
            }
        }
        #pragma unroll
        for (int s = 16; s; s >>= 1) {
            float od = __shfl_xor_sync(0xffffffffu, bdd, s);
            int   oi = __shfl_xor_sync(0xffffffffu, bii, s);
            if (od < bdd || (od == bdd && oi < bii)) { bdd = od; bii = oi; }
        }
        if (lane == 0) {
            g_idx[row0 + r] = bii;
            red[384 + r] = bdd;               // winner's exact squared distance
        }
    }

    // deterministic per-block loss partial
    __syncthreads();
    for (int o = 64; o; o >>= 1) {
        if (tid < o) red[384 + tid] += red[384 + tid + o];
        __syncthreads();
    }
    if (tid == 0) g_partial[blockIdx.x] = red[384];
}

// ---------------- U = cn @ w_out^T + b_out (per page, once) ----------------
__global__ __launch_bounds__(256, 2) void u_kernel(const float* __restrict__ b_out) {
    extern __shared__ float sm[];
    float* codeS = sm;          // 8192 floats: [128 pages][64]
    float* wS = sm + 8192;      // 8192 floats: [64][128]
    int tid = threadIdx.x, tx = tid & 15, ty = tid >> 4;
    int f0 = blockIdx.x * 128;
    int p0 = blockIdx.y * 128;
    for (int i = tid; i < 8192; i += 256) {
        int r = i >> 6, c = i & 63;
        codeS[r * 64 + c] = g_cn[(p0 + r) * 64 + c];
    }
    for (int i = tid; i < 8192; i += 256) {
        int c = i >> 7, f = i & 127;
        wS[c * 128 + f] = g_woutT[c * 768 + f0 + f];
    }
    __syncthreads();
    float acc[8][8];
    #pragma unroll
    for (int i = 0; i < 8; i++)
        #pragma unroll
        for (int j = 0; j < 8; j++) acc[i][j] = 0.f;
    #pragma unroll 4
    for (int c = 0; c < 64; c++) {
        float a[8], b[8];
        #pragma unroll
        for (int i = 0; i < 8; i++) a[i] = codeS[(ty + 16 * i) * 64 + c];
        #pragma unroll
        for (int j = 0; j < 8; j++) b[j] = wS[c * 128 + tx + 16 * j];
        #pragma unroll
        for (int i = 0; i < 8; i++)
            #pragma unroll
            for (int j = 0; j < 8; j++)
                acc[i][j] = fmaf(a[i], b[j], acc[i][j]);
    }
    float bo[8];
    #pragma unroll
    for (int j = 0; j < 8; j++) bo[j] = b_out[f0 + tx + 16 * j];
    #pragma unroll
    for (int i = 0; i < 8; i++)
        #pragma unroll
        for (int j = 0; j < 8; j++)
            g_U[(p0 + ty + 16 * i) * 768 + f0 + tx + 16 * j] = acc[i][j] + bo[j];
}

// ---------------- out[n] = U[idx[n]] (pure gather, float4) -----------------
__global__ void gather_kernel(float* __restrict__ out) {
    int n = blockIdx.x;
    int t = threadIdx.x;          // 192 threads, 192 float4 = 768 floats
    const float4* src = (const float4*)(g_U + g_idx[n] * 768);
    float4* dst = (float4*)(out + (long)n * 768);
    dst[t] = src[t];
}

__global__ void finalize_kernel(float* __restrict__ outbuf) {
    if (threadIdx.x == 0) {
        float s = 0.f;
        for (int k = 0; k < 256; k++) s += g_partial[k];
        outbuf[OFF_LOSS] = 1.25f * (s / 2097152.0f);
    }
}

__global__ void idx_kernel(float* __restrict__ outbuf) {
    int i = blockIdx.x * 256 + threadIdx.x;
    outbuf[OFF_IDX + i] = (float)g_idx[i];
}

// ---------------- launch ----------------------------------------------------
extern "C" void kernel_launch(void* const* d_in, const int* in_sizes, int n_in,
                              void* d_out, int out_size) {
    const float* z     = (const float*)d_in[0];
    const float* w_in  = (const float*)d_in[1];
    const float* b_in  = (const float*)d_in[2];
    const float* w_out = (const float*)d_in[3];
    const float* b_out = (const float*)d_in[4];
    const float* cb    = (const float*)d_in[5];
    float* out = (float*)d_out;

    cudaFuncSetAttribute(zq_kernel, cudaFuncAttributeMaxDynamicSharedMemorySize, 104448);
    cudaFuncSetAttribute(argmin_kernel, cudaFuncAttributeMaxDynamicSharedMemorySize, SM_TOTAL);
    cudaFuncSetAttribute(u_kernel, cudaFuncAttributeMaxDynamicSharedMemorySize, 65536);

    cb_norm_kernel<<<PAGES / 4, 256>>>(cb);
    prep_w_kernel<<<FEAT * CODES / 256, 256>>>(w_in, w_out);
    u_kernel<<<dim3(6, PAGES / 128), 256, 65536>>>(b_out);
    zq_kernel<<<N_SAMPLES / 128, 256, 104448>>>(z, b_in);
    argmin_kernel<<<N_SAMPLES / 128, 256, SM_TOTAL>>>();
    gather_kernel<<<N_SAMPLES, 192>>>(out);
    finalize_kernel<<<1, 1>>>(out);
    idx_kernel<<<N_SAMPLES / 256, 256>>>(out);
}